// round 4
// baseline (speedup 1.0000x reference)
#include <cuda_runtime.h>

// SSIM_79886391705722 — fused separable-Gaussian SSIM, f32x2, strip-8,
// LDS.128 h-planes. GB300 sm_103a.
// raw/dst: [32,3,512,512] f32. Crop 4 -> *255 -> 11x11 gaussian (valid)
// -> 494x494 SSIM map -> per-batch mean [32].

typedef unsigned long long u64;

#define TILE_W  32
#define TILE_H  40
#define IN_W    42
#define IN_H    50
#define P_RD    43     // u64 pitch (odd) -> conflict-free for y-consecutive lanes
#define P_H     33     // 16B-pair pitch (odd)
#define OUT_DIM 494
#define CROP_LAST 507

// Normalized 1D Gaussian (ws=11, sigma=1.5); symmetric: g[j] = gv[min(j,10-j)]
#define G0 0.00102838f
#define G1 0.00759875f
#define G2 0.03600078f
#define G3 0.10936070f
#define G4 0.21300554f
#define G5 0.26601173f

__device__ __forceinline__ u64 pack2(float lo, float hi) {
    u64 r; asm("mov.b64 %0, {%1,%2};" : "=l"(r) : "f"(lo), "f"(hi)); return r;
}
__device__ __forceinline__ void unpack2(u64 v, float& lo, float& hi) {
    asm("mov.b64 {%0,%1}, %2;" : "=f"(lo), "=f"(hi) : "l"(v));
}
__device__ __forceinline__ u64 mul2(u64 a, u64 b) {
    u64 r; asm("mul.rn.f32x2 %0, %1, %2;" : "=l"(r) : "l"(a), "l"(b)); return r;
}
__device__ __forceinline__ u64 fma2(u64 a, u64 b, u64 c) {
    u64 r; asm("fma.rn.f32x2 %0, %1, %2, %3;" : "=l"(r) : "l"(a), "l"(b), "l"(c)); return r;
}

__global__ __launch_bounds__(32) void ssim_zero(float* out) {
    out[threadIdx.x] = 0.0f;
}

__global__ __launch_bounds__(256) void ssim_main(const float* __restrict__ raw,
                                                 const float* __restrict__ dst,
                                                 float* __restrict__ out) {
    __shared__ u64        s_rd[IN_H * P_RD];           // (r,d)      17.2KB
    __shared__ ulonglong2 s_h[IN_H * P_H];             // {m, q}     26.4KB
    __shared__ float      s_red[8];

    const int tid = threadIdx.x;
    const int z   = blockIdx.z;                  // b*3 + c
    const size_t plane = (size_t)z * 512 * 512;
    const float* rp = raw + plane;
    const float* dp = dst + plane;

    const float gv[6] = {G0, G1, G2, G3, G4, G5};
    u64 g2v[6];
    #pragma unroll
    for (int i = 0; i < 6; i++) g2v[i] = pack2(gv[i], gv[i]);
    #define GW(j)  gv[(j) < 6 ? (j) : 10 - (j)]
    #define GW2(j) g2v[(j) < 6 ? (j) : 10 - (j)]

    // ---- Phase 1: load 50x42 halo of (r,d)*255, packed u64 ----
    const int row0 = blockIdx.y * TILE_H + 4;
    const int col0 = blockIdx.x * TILE_W + 4;    // even -> float2 aligned
    for (int i = tid; i < IN_H * 21; i += 256) {
        int y  = i / 21;
        int xp = i - y * 21;
        int x  = xp * 2;
        int gr = row0 + y, gc = col0 + x;
        float r0 = 0.f, r1 = 0.f, d0 = 0.f, d1 = 0.f;
        if (gr <= CROP_LAST && gc <= CROP_LAST) {
            size_t off = (size_t)gr * 512 + gc;  // gc+1 <= 511 always in-plane
            float2 rv = *reinterpret_cast<const float2*>(rp + off);
            float2 dv = *reinterpret_cast<const float2*>(dp + off);
            r0 = rv.x * 255.0f; d0 = dv.x * 255.0f;
            if (gc + 1 <= CROP_LAST) { r1 = rv.y * 255.0f; d1 = dv.y * 255.0f; }
        }
        s_rd[y * P_RD + x]     = pack2(r0, d0);
        s_rd[y * P_RD + x + 1] = pack2(r1, d1);
    }
    __syncthreads();

    // ---- Phase 2: horizontal 11-tap, strips of 8; 4 strips x 50 rows ----
    // warp w: x0 = (w&3)*8; y = lane + 32*(w>>2). Conflict-free (odd pitches).
    {
        int w    = tid >> 5;
        int lane = tid & 31;
        int x0   = (w & 3) << 3;
        int y    = lane + ((w >> 2) << 5);
        if (y < IN_H) {
            const u64* base = &s_rd[y * P_RD + x0];
            u64 am[8], aq[8];
            #pragma unroll
            for (int k = 0; k < 8; k++) { am[k] = 0; aq[k] = 0; }
            #pragma unroll
            for (int i = 0; i < 18; i++) {
                u64 v  = base[i];
                u64 sq = mul2(v, v);
                float r, d, rr, dd;
                unpack2(v, r, d);
                unpack2(sq, rr, dd);
                u64 q = pack2(rr + dd, r * d);
                #pragma unroll
                for (int k = 0; k < 8; k++) {
                    int j = i - k;
                    if (j >= 0 && j < 11) {
                        am[k] = fma2(GW2(j), v, am[k]);
                        aq[k] = fma2(GW2(j), q, aq[k]);
                    }
                }
            }
            int hb = y * P_H + x0;
            #pragma unroll
            for (int k = 0; k < 8; k++) {
                ulonglong2 hp; hp.x = am[k]; hp.y = aq[k];
                s_h[hb + k] = hp;
            }
        }
    }
    __syncthreads();

    // ---- Phase 3: vertical 11-tap, strips of 8 + SSIM + reduce ----
    // warps 0..4: y0 = w*8, x = lane. LDS.128 reads, conflict-free.
    float local = 0.0f;
    {
        int w    = tid >> 5;
        int lane = tid & 31;
        if (w < 5) {
            int y0 = w << 3;
            const ulonglong2* bh = &s_h[y0 * P_H + lane];
            u64 am[8], aq[8];
            #pragma unroll
            for (int k = 0; k < 8; k++) { am[k] = 0; aq[k] = 0; }
            #pragma unroll
            for (int j = 0; j < 18; j++) {
                ulonglong2 hp = bh[j * P_H];
                #pragma unroll
                for (int k = 0; k < 8; k++) {
                    int t = j - k;
                    if (t >= 0 && t < 11) {
                        am[k] = fma2(GW2(t), hp.x, am[k]);
                        aq[k] = fma2(GW2(t), hp.y, aq[k]);
                    }
                }
            }
            const float C1 = 6.5025f;
            const float C2 = 58.5225f;
            int ox  = blockIdx.x * TILE_W + lane;
            int oyb = blockIdx.y * TILE_H + y0;
            if (ox < OUT_DIM) {
                #pragma unroll
                for (int k = 0; k < 8; k++) {
                    if ((oyb + k) < OUT_DIM) {
                        float a, b, srrdd, srd;
                        unpack2(am[k], a, b);
                        unpack2(aq[k], srrdd, srd);
                        float ab  = a * b;
                        float cov = srd - ab;
                        float var = srrdd - a * a - b * b;
                        float num = (2.0f * ab + C1) * (2.0f * cov + C2);
                        float den = (a * a + b * b + C1) * (var + C2);
                        local += __fdividef(num, den);
                    }
                }
            }
        }
    }

    #pragma unroll
    for (int o = 16; o > 0; o >>= 1)
        local += __shfl_down_sync(0xffffffff, local, o);
    if ((tid & 31) == 0) s_red[tid >> 5] = local;
    __syncthreads();
    if (tid < 8) {
        local = s_red[tid];
        #pragma unroll
        for (int o = 4; o > 0; o >>= 1)
            local += __shfl_down_sync(0xff, local, o);
        if (tid == 0)
            atomicAdd(&out[z / 3], local * (1.0f / 732108.0f)); // 1/(3*494^2)
    }
}

extern "C" void kernel_launch(void* const* d_in, const int* in_sizes, int n_in,
                              void* d_out, int out_size) {
    const float* raw = (const float*)d_in[0];
    const float* dst = (const float*)d_in[1];
    float* out = (float*)d_out;

    ssim_zero<<<1, 32>>>(out);
    dim3 grid(16, 13, 96);   // 32x40 tiles over 494x494, z = b*3+c
    ssim_main<<<grid, 256>>>(raw, dst, out);
}

// round 5
// speedup vs baseline: 1.1225x; 1.1225x over previous
#include <cuda_runtime.h>

// SSIM_79886391705722 — fused separable-Gaussian SSIM, f32x2, balanced tasks
// (R3 decomposition) + LDS.128 packed h-planes. GB300 sm_103a.
// raw/dst: [32,3,512,512] f32. Crop 4 -> *255 -> 11x11 gaussian (valid)
// -> 494x494 SSIM map -> per-batch mean [32].

typedef unsigned long long u64;

#define TILE_W  32
#define TILE_H  40
#define IN_H    50
#define P_RD    43     // u64 pitch (odd) -> conflict-free for y-consecutive lanes
#define P_H     33     // ulonglong2 pitch (odd)
#define OUT_DIM 494
#define CROP_LAST 507

// Normalized 1D Gaussian (ws=11, sigma=1.5); symmetric: g[j] = gv[min(j,10-j)]
#define G0 0.00102838f
#define G1 0.00759875f
#define G2 0.03600078f
#define G3 0.10936070f
#define G4 0.21300554f
#define G5 0.26601173f

__device__ __forceinline__ u64 pack2(float lo, float hi) {
    u64 r; asm("mov.b64 %0, {%1,%2};" : "=l"(r) : "f"(lo), "f"(hi)); return r;
}
__device__ __forceinline__ void unpack2(u64 v, float& lo, float& hi) {
    asm("mov.b64 {%0,%1}, %2;" : "=f"(lo), "=f"(hi) : "l"(v));
}
__device__ __forceinline__ u64 mul2(u64 a, u64 b) {
    u64 r; asm("mul.rn.f32x2 %0, %1, %2;" : "=l"(r) : "l"(a), "l"(b)); return r;
}
__device__ __forceinline__ u64 fma2(u64 a, u64 b, u64 c) {
    u64 r; asm("fma.rn.f32x2 %0, %1, %2, %3;" : "=l"(r) : "l"(a), "l"(b), "l"(c)); return r;
}

__global__ __launch_bounds__(32) void ssim_zero(float* out) {
    out[threadIdx.x] = 0.0f;
}

__global__ __launch_bounds__(256) void ssim_main(const float* __restrict__ raw,
                                                 const float* __restrict__ dst,
                                                 float* __restrict__ out) {
    __shared__ u64        s_rd[IN_H * P_RD];   // (r,d)         17.2KB
    __shared__ ulonglong2 s_h[IN_H * P_H];     // {m=(mr,md), q=(rr+dd,rd)} 26.4KB
    __shared__ float      s_red[8];

    const int tid = threadIdx.x;
    const int z   = blockIdx.z;                  // b*3 + c
    const size_t plane = (size_t)z * 512 * 512;
    const float* rp = raw + plane;
    const float* dp = dst + plane;

    const float gv[6] = {G0, G1, G2, G3, G4, G5};
    u64 g2v[6];
    #pragma unroll
    for (int i = 0; i < 6; i++) g2v[i] = pack2(gv[i], gv[i]);
    #define GW2(j) g2v[(j) < 6 ? (j) : 10 - (j)]

    // ---- Phase 1: load 50x42 halo of (r,d)*255, packed u64 ----
    const int row0 = blockIdx.y * TILE_H + 4;
    const int col0 = blockIdx.x * TILE_W + 4;    // even -> float2 aligned
    for (int i = tid; i < IN_H * 21; i += 256) {
        int y  = i / 21;
        int xp = i - y * 21;
        int x  = xp * 2;
        int gr = row0 + y, gc = col0 + x;
        float r0 = 0.f, r1 = 0.f, d0 = 0.f, d1 = 0.f;
        if (gr <= CROP_LAST && gc <= CROP_LAST) {
            size_t off = (size_t)gr * 512 + gc;  // gc+1 <= 511 always in-plane
            float2 rv = *reinterpret_cast<const float2*>(rp + off);
            float2 dv = *reinterpret_cast<const float2*>(dp + off);
            r0 = rv.x * 255.0f; d0 = dv.x * 255.0f;
            if (gc + 1 <= CROP_LAST) { r1 = rv.y * 255.0f; d1 = dv.y * 255.0f; }
        }
        s_rd[y * P_RD + x]     = pack2(r0, d0);
        s_rd[y * P_RD + x + 1] = pack2(r1, d1);
    }
    __syncthreads();

    // ---- Phase 2: horizontal 11-tap, strips of 4; 8 strips x 50 rows ----
    // Half-warp = 16 consecutive y at one strip -> conflict-free, no swizzle.
    for (int task = tid; task < 512; task += 256) {
        int y = (task & 15) | ((task >> 7) << 4);
        if (y < IN_H) {
            int x0 = ((task >> 4) & 7) << 2;
            const u64* base = &s_rd[y * P_RD + x0];
            u64 am[4] = {0, 0, 0, 0};
            u64 aq[4] = {0, 0, 0, 0};
            #pragma unroll
            for (int i = 0; i < 14; i++) {
                u64 v  = base[i];
                u64 sq = mul2(v, v);
                float r, d, rr, dd;
                unpack2(v, r, d);
                unpack2(sq, rr, dd);
                u64 q = pack2(rr + dd, r * d);
                #pragma unroll
                for (int k = 0; k < 4; k++) {
                    int j = i - k;
                    if (j >= 0 && j < 11) {
                        am[k] = fma2(GW2(j), v, am[k]);
                        aq[k] = fma2(GW2(j), q, aq[k]);
                    }
                }
            }
            int hb = y * P_H + x0;
            #pragma unroll
            for (int k = 0; k < 4; k++) {
                ulonglong2 hp; hp.x = am[k]; hp.y = aq[k];
                s_h[hb + k] = hp;
            }
        }
    }
    __syncthreads();

    // ---- Phase 3: vertical 11-tap, strips of 5 + SSIM + reduce (256 tasks) ----
    float local = 0.0f;
    {
        int x  = tid & 31;
        int y0 = (tid >> 5) * 5;
        u64 am[5] = {0, 0, 0, 0, 0};
        u64 aq[5] = {0, 0, 0, 0, 0};
        const ulonglong2* bh = &s_h[y0 * P_H + x];
        #pragma unroll
        for (int j = 0; j < 15; j++) {
            ulonglong2 hp = bh[j * P_H];
            #pragma unroll
            for (int k = 0; k < 5; k++) {
                int t = j - k;
                if (t >= 0 && t < 11) {
                    am[k] = fma2(GW2(t), hp.x, am[k]);
                    aq[k] = fma2(GW2(t), hp.y, aq[k]);
                }
            }
        }
        const float C1 = 6.5025f;
        const float C2 = 58.5225f;
        int ox  = blockIdx.x * TILE_W + x;
        int oyb = blockIdx.y * TILE_H + y0;
        if (ox < OUT_DIM) {
            #pragma unroll
            for (int k = 0; k < 5; k++) {
                if ((oyb + k) < OUT_DIM) {
                    float a, b, srrdd, srd;
                    unpack2(am[k], a, b);
                    unpack2(aq[k], srrdd, srd);
                    float ab  = a * b;
                    float cov = srd - ab;
                    float var = srrdd - a * a - b * b;
                    float num = (2.0f * ab + C1) * (2.0f * cov + C2);
                    float den = (a * a + b * b + C1) * (var + C2);
                    local += __fdividef(num, den);
                }
            }
        }
    }

    #pragma unroll
    for (int o = 16; o > 0; o >>= 1)
        local += __shfl_down_sync(0xffffffff, local, o);
    if ((tid & 31) == 0) s_red[tid >> 5] = local;
    __syncthreads();
    if (tid < 8) {
        local = s_red[tid];
        #pragma unroll
        for (int o = 4; o > 0; o >>= 1)
            local += __shfl_down_sync(0xff, local, o);
        if (tid == 0)
            atomicAdd(&out[z / 3], local * (1.0f / 732108.0f)); // 1/(3*494^2)
    }
}

extern "C" void kernel_launch(void* const* d_in, const int* in_sizes, int n_in,
                              void* d_out, int out_size) {
    const float* raw = (const float*)d_in[0];
    const float* dst = (const float*)d_in[1];
    float* out = (float*)d_out;

    ssim_zero<<<1, 32>>>(out);
    dim3 grid(16, 13, 96);   // 32x40 tiles over 494x494, z = b*3+c
    ssim_main<<<grid, 256>>>(raw, dst, out);
}